// round 16
// baseline (speedup 1.0000x reference)
#include <cuda_runtime.h>
#include <cuda.h>
#include <cstdint>
#include <math.h>

#define BATCH   16
#define NCLS    64
#define CDF     128
#define EDIM    1024

// ===================== common helpers =====================
__device__ __forceinline__ uint32_t f2tf32(float f) {
    uint32_t u; asm("cvt.rna.tf32.f32 %0, %1;" : "=r"(u) : "f"(f)); return u;
}
__device__ __forceinline__ float gelu_erf(float v) {
    return 0.5f * v * (1.0f + erff(v * 0.7071067811865476f));
}

#if defined(__CUDA_ARCH_FEAT_SM103_ALL) || defined(__CUDA_ARCH_FEAT_SM100_ALL) || defined(__CUDA_ARCH_FEAT_SM101_ALL)
#define TCGEN05_OK 1
#else
#define TCGEN05_OK 0
#endif

// 256MB scratch: W1 transposed + tf32-RNA rounded, layout [c][n][k]
__device__ float g_W1t[(size_t)NCLS * EDIM * EDIM];

// ======================================================================
// Kernel 0: W1 [c][k][n] -> g_W1t [c][n][k], tf32-RNA (32x32 transpose)
// ======================================================================
__global__ void __launch_bounds__(256)
w1_conv(const float* __restrict__ W1) {
    __shared__ float t[32][33];
    const int c  = blockIdx.z;
    const int k0 = blockIdx.x * 32;
    const int n0 = blockIdx.y * 32;
    const float* src = W1 + ((size_t)c << 20);
    float*       dst = g_W1t + ((size_t)c << 20);
    const int tx = threadIdx.x, ty = threadIdx.y;   // 32 x 8
    #pragma unroll
    for (int i = 0; i < 4; ++i)
        t[ty + i * 8][tx] = src[(size_t)(k0 + ty + i * 8) * EDIM + n0 + tx];
    __syncthreads();
    #pragma unroll
    for (int i = 0; i < 4; ++i) {
        float v = t[tx][ty + i * 8];
        dst[(size_t)(n0 + ty + i * 8) * EDIM + k0 + tx] = __uint_as_float(f2tf32(v));
    }
}

// ======================================================================
// cg1 tcgen05 tf32 GEMM, M=256 via TWO batches per CTA sharing one B tile:
//   bytes/MAC -33% vs M=128. Two 128-row MMA halves -> two 256-col TMEM
//   D regions (512 cols total, 1 CTA/SM). KT=32, NSTAGE=3 (64KB/stage).
//   A: LDG+cvt+STS prefetch (both batch slabs). B: local unicast TMA.
// ======================================================================
#define NCHUNK  256        // N columns per chunk (4 chunks total)
#define KT      32         // K per stage (4 tcgen05 K=8 dispatches per M-half)
#define NSTAGE  3
#define THREADS_TC 288     // warps 0-3 epilogue, 4-7 A-stagers, 8 MMA
#define A_TILE_BYTES 32768u   // 256 rows x 32k x 4B (two 16KB halves)
#define A_HALF_BYTES 16384u
#define B_TILE_BYTES 32768u   // 256 n x 32k x 4B

#define OFF_TMEM   0
#define OFF_MB     8                     // stage s: full @ 8+16s, empty @ 8+16s+8
#define OFF_CHK    72                    // chunk_done (single mbar)
#define OFF_EPI    88                    // epi_done   (single mbar)
#define OFF_SB1    128                   // float[1024]
#define OFF_SW2    (128 + 4096)          // float[1024]
#define OFF_TILE   9216                  // 1KB aligned
#define STAGE_BYTES 65536                // A 32KB + B 32KB
#define BTILE_OFF   32768
#define SMEM_TOTAL (OFF_TILE + NSTAGE * STAGE_BYTES)   // 205824 -> 1 CTA/SM

#define TMEM_COLS 512

// idesc: kind::tf32, D=F32(1)@[4], atype=TF32(2)@[7], btype=TF32(2)@[10],
// N>>3 @[17] (N=256), M>>4 @[24] (M=128 per half)
#define IDESC_TF32 ((1u<<4) | (2u<<7) | (2u<<10) | ((NCHUNK/8)<<17) | ((128/16)<<24))

#if TCGEN05_OK
__device__ __forceinline__ uint64_t make_desc(uint32_t addr) {
    return (uint64_t(2) << 61) | (uint64_t(1) << 46) | (uint64_t(64) << 32)
         | (uint64_t(1) << 16) | ((uint64_t)(addr >> 4) & 0x3FFF);
}
__device__ __forceinline__ uint32_t smem_u32(const void* p) {
    uint32_t a;
    asm("{ .reg .u64 t; cvta.to.shared.u64 t, %1; cvt.u32.u64 %0, t; }" : "=r"(a) : "l"(p));
    return a;
}
__device__ __forceinline__ void sts128(uint32_t a, uint32_t x, uint32_t y, uint32_t z, uint32_t w) {
    asm volatile("st.shared.v4.b32 [%0], {%1,%2,%3,%4};" :: "r"(a), "r"(x), "r"(y), "r"(z), "r"(w) : "memory");
}
__device__ __forceinline__ void mbar_init(uint32_t a, uint32_t cnt) {
    asm volatile("mbarrier.init.shared.b64 [%0], %1;" :: "r"(a), "r"(cnt) : "memory");
}
__device__ __forceinline__ void mbar_arrive(uint32_t a) {
    asm volatile("mbarrier.arrive.shared.b64 _, [%0];" :: "r"(a) : "memory");
}
__device__ __forceinline__ void mbar_wait(uint32_t a, uint32_t parity) {
    asm volatile(
        "{\n\t.reg .pred P;\n\t"
        "WL%=:\n\t"
        "mbarrier.try_wait.parity.acquire.cta.shared::cta.b64 P, [%0], %1, 0x989680;\n\t"
        "@P bra.uni WD%=;\n\t"
        "bra.uni WL%=;\n\t"
        "WD%=:\n\t}" :: "r"(a), "r"(parity) : "memory");
}
__device__ __forceinline__ void fence_async_proxy() {
    asm volatile("fence.proxy.async.shared::cta;" ::: "memory");
}
__device__ __forceinline__ void tc_commit(uint32_t mbar) {
    asm volatile("tcgen05.commit.cta_group::1.mbarrier::arrive::one.shared::cluster.b64 [%0];"
                 :: "r"(mbar) : "memory");
}
__device__ __forceinline__ void mma_tf32_ss(uint32_t d, uint64_t ad, uint64_t bd,
                                            uint32_t idesc, uint32_t enable) {
    asm volatile(
        "{\n\t.reg .pred p;\n\t"
        "setp.ne.u32 p, %5, 0;\n\t"
        "tcgen05.mma.cta_group::1.kind::tf32 [%0], %1, %2, %3, {%4,%4,%4,%4}, p;\n\t}"
        :: "r"(d), "l"(ad), "l"(bd), "r"(idesc), "r"(0u), "r"(enable) : "memory");
}
#endif  // TCGEN05_OK

__global__ void __launch_bounds__(THREADS_TC, 1)
mlp_head_tc(const __grid_constant__ CUtensorMap tmapB,
            const float* __restrict__ x,
            const float* __restrict__ b1,
            const float* __restrict__ W2,
            const float* __restrict__ b2,
            float* __restrict__ out)
{
#if TCGEN05_OK
    extern __shared__ char smem[];
    const uint32_t sb = smem_u32(smem);

    const int tid  = threadIdx.x;
    const int warp = tid >> 5;
    const int lane = tid & 31;
    const int b0   = blockIdx.x * 2;       // two batches per CTA
    const int c    = blockIdx.y;

    const float* Abase0 = x + ((size_t)b0       * (NCLS * CDF) + (size_t)c * CDF) * EDIM;
    const float* Abase1 = x + ((size_t)(b0 + 1) * (NCLS * CDF) + (size_t)c * CDF) * EDIM;

    float* sb1s = (float*)(smem + OFF_SB1);
    float* sw2s = (float*)(smem + OFF_SW2);

    if (warp == 8) {
        asm volatile("tcgen05.alloc.cta_group::1.sync.aligned.shared::cta.b32 [%0], %1;"
                     :: "r"(sb + OFF_TMEM), "r"((uint32_t)TMEM_COLS) : "memory");
        asm volatile("tcgen05.relinquish_alloc_permit.cta_group::1.sync.aligned;" ::: "memory");
    }
    if (tid == 0) {
        #pragma unroll
        for (int s = 0; s < NSTAGE; ++s) {
            mbar_init(sb + OFF_MB + s * 16,     129);   // full: 128 stagers + expect_tx
            mbar_init(sb + OFF_MB + s * 16 + 8, 1);     // empty: 1 commit
        }
        mbar_init(sb + OFF_CHK, 1);     // chunk done (flips per chunk)
        mbar_init(sb + OFF_EPI, 128);   // epilogue done with D buffers
    }
    __syncthreads();

    uint32_t tmem;
    asm volatile("ld.shared.b32 %0, [%1];" : "=r"(tmem) : "r"(sb + OFF_TMEM));

    const int NTILES = 4 * (EDIM / KT);   // 128 stages (4 n-chunks x 32 k-tiles)

    if (warp >= 4 && warp < 8) {
        // ===== PRODUCERS (warps 4-7): A LDG+cvt+STS (2 slabs), B unicast TMA =====
        const int local = tid - 128;
        const int q  = local & 7;    // 16B quad within 128B row
        const int r8 = local >> 3;   // 0..15

        float4 abuf[16];   // 16 row-passes: 8 per batch half
        auto load_a = [&](int g) {
            const int gi = (g < NTILES) ? g : (NTILES - 1);
            const int k0 = (gi & 31) * KT;
            const float* Ak0 = Abase0 + k0 + (size_t)r8 * EDIM + q * 4;
            const float* Ak1 = Abase1 + k0 + (size_t)r8 * EDIM + q * 4;
            #pragma unroll
            for (int ps = 0; ps < 8; ++ps) {
                abuf[ps]     = *(const float4*)(Ak0 + (size_t)ps * 16 * EDIM);
                abuf[8 + ps] = *(const float4*)(Ak1 + (size_t)ps * 16 * EDIM);
            }
        };

        load_a(0);
        for (int g = 0; g < NTILES; ++g) {
            const int s = g % NSTAGE;
            const int r = g / NSTAGE;
            const uint32_t fullb  = sb + OFF_MB + s * 16;
            const uint32_t emptyb = fullb + 8;
            mbar_wait(emptyb, (r & 1) ^ 1);   // MMA done with stage s

            const uint32_t a_sm = sb + OFF_TILE + s * STAGE_BYTES;
            const uint32_t b_sm = a_sm + BTILE_OFF;

            if (local == 0) {
                asm volatile("mbarrier.arrive.expect_tx.shared.b64 _, [%0], %1;"
                             :: "r"(fullb), "r"(B_TILE_BYTES) : "memory");
                const int k0 = (g & 31) * KT;
                const int ng = (g >> 5) * NCHUNK;      // n-chunk base
                asm volatile(
                    "cp.async.bulk.tensor.3d.shared::cta.global.tile"
                    ".mbarrier::complete_tx::bytes "
                    "[%0], [%1, {%2, %3, %4}], [%5];"
                    :: "r"(b_sm), "l"(&tmapB),
                       "r"(k0), "r"(ng), "r"(c), "r"(fullb) : "memory");
            }

            // A tiles: two halves of 128 rows x 32 k, tf32-RNA, SW128
            #pragma unroll
            for (int h = 0; h < 2; ++h) {
                #pragma unroll
                for (int ps = 0; ps < 8; ++ps) {
                    const int row = ps * 16 + r8;
                    uint32_t off = row * 128 + q * 16;
                    off ^= (off >> 3) & 0x70;
                    const float4 v = abuf[h * 8 + ps];
                    sts128(a_sm + h * A_HALF_BYTES + off,
                           f2tf32(v.x), f2tf32(v.y), f2tf32(v.z), f2tf32(v.w));
                }
            }
            fence_async_proxy();
            mbar_arrive(fullb);
            load_a(g + 1);
        }
    } else if (warp == 8) {
        // ================= MMA ISSUE (warp 8, lane 0) =================
        if (lane == 0) {
            uint64_t ad[NSTAGE][2], bd[NSTAGE];
            #pragma unroll
            for (int s = 0; s < NSTAGE; ++s) {
                ad[s][0] = make_desc(sb + OFF_TILE + s * STAGE_BYTES);
                ad[s][1] = make_desc(sb + OFF_TILE + s * STAGE_BYTES + A_HALF_BYTES);
                bd[s]    = make_desc(sb + OFF_TILE + s * STAGE_BYTES + BTILE_OFF);
            }
            int g = 0;
            for (int ci = 0; ci < 4; ++ci) {
                if (ci >= 1) {
                    // wait for epilogue to drain both D regions
                    mbar_wait(sb + OFF_EPI, (ci - 1) & 1);
                    asm volatile("tcgen05.fence::after_thread_sync;" ::: "memory");
                }
                for (int kt = 0; kt < 32; ++kt, ++g) {
                    const int s = g % NSTAGE;
                    const int r = g / NSTAGE;
                    mbar_wait(sb + OFF_MB + s * 16, r & 1);   // full
                    #pragma unroll
                    for (int h = 0; h < 2; ++h) {
                        const uint32_t dt = tmem + h * NCHUNK;
                        #pragma unroll
                        for (int j = 0; j < 4; ++j) {
                            mma_tf32_ss(dt, ad[s][h] + j * 2, bd[s] + j * 2,
                                        IDESC_TF32, (kt > 0 || j > 0) ? 1u : 0u);
                        }
                    }
                    tc_commit(sb + OFF_MB + s * 16 + 8);      // -> empty
                }
                tc_commit(sb + OFF_CHK);                      // chunk done
            }
        }
    } else {
        // ================= EPILOGUE (warps 0-3, 128 threads) =================
        #pragma unroll
        for (int i = 0; i < 8; ++i) {
            sb1s[tid + i * 128] = b1[(size_t)c * EDIM + tid + i * 128];
            sw2s[tid + i * 128] = W2[(size_t)c * EDIM + tid + i * 128];
        }
        asm volatile("bar.sync 1, 128;" ::: "memory");

        float acc0 = 0.0f, acc1 = 0.0f;
        for (int ci = 0; ci < 4; ++ci) {
            mbar_wait(sb + OFF_CHK, ci & 1);
            asm volatile("tcgen05.fence::after_thread_sync;" ::: "memory");

            #pragma unroll
            for (int h = 0; h < 2; ++h) {
                #pragma unroll
                for (int blk = 0; blk < NCHUNK / 32; ++blk) {
                    uint32_t rg[32];
                    asm volatile(
                        "tcgen05.ld.sync.aligned.32x32b.x32.b32 "
                        "{%0,%1,%2,%3,%4,%5,%6,%7,%8,%9,%10,%11,%12,%13,%14,%15,"
                        "%16,%17,%18,%19,%20,%21,%22,%23,%24,%25,%26,%27,%28,%29,%30,%31}, [%32];"
                        : "=r"(rg[0]),"=r"(rg[1]),"=r"(rg[2]),"=r"(rg[3]),"=r"(rg[4]),"=r"(rg[5]),
                          "=r"(rg[6]),"=r"(rg[7]),"=r"(rg[8]),"=r"(rg[9]),"=r"(rg[10]),"=r"(rg[11]),
                          "=r"(rg[12]),"=r"(rg[13]),"=r"(rg[14]),"=r"(rg[15]),"=r"(rg[16]),"=r"(rg[17]),
                          "=r"(rg[18]),"=r"(rg[19]),"=r"(rg[20]),"=r"(rg[21]),"=r"(rg[22]),"=r"(rg[23]),
                          "=r"(rg[24]),"=r"(rg[25]),"=r"(rg[26]),"=r"(rg[27]),"=r"(rg[28]),"=r"(rg[29]),
                          "=r"(rg[30]),"=r"(rg[31])
                        : "r"(tmem + h * NCHUNK + blk * 32));
                    asm volatile("tcgen05.wait::ld.sync.aligned;" ::: "memory");
                    float part = 0.0f;
                    #pragma unroll
                    for (int j = 0; j < 32; ++j) {
                        const int col = ci * NCHUNK + blk * 32 + j;
                        float v = __uint_as_float(rg[j]) + sb1s[col];
                        part += gelu_erf(v) * sw2s[col];
                    }
                    if (h == 0) acc0 += part; else acc1 += part;
                }
            }
            asm volatile("tcgen05.fence::before_thread_sync;" ::: "memory");
            mbar_arrive(sb + OFF_EPI);   // D buffers free for next chunk
        }
        const int row = warp * 32 + lane;
        out[(size_t)b0       * (NCLS * CDF) + (size_t)c * CDF + row] = acc0 + b2[c];
        out[(size_t)(b0 + 1) * (NCLS * CDF) + (size_t)c * CDF + row] = acc1 + b2[c];
    }

    __syncthreads();
    if (warp == 8) {
        asm volatile("tcgen05.dealloc.cta_group::1.sync.aligned.b32 %0, %1;"
                     :: "r"(tmem), "r"((uint32_t)TMEM_COLS));
    }
#else
    (void)tmapB; (void)x; (void)b1; (void)W2; (void)b2; (void)out;
#endif
}

// ======================================================================
// Host
// ======================================================================
typedef CUresult (*EncodeFn)(CUtensorMap*, CUtensorMapDataType, cuuint32_t, void*,
                             const cuuint64_t*, const cuuint64_t*, const cuuint32_t*,
                             const cuuint32_t*, CUtensorMapInterleave, CUtensorMapSwizzle,
                             CUtensorMapL2promotion, CUtensorMapFloatOOBfill);
static EncodeFn get_encoder() {
    EncodeFn fn = nullptr;
    cudaDriverEntryPointQueryResult qr;
#if CUDART_VERSION >= 12050
    cudaGetDriverEntryPointByVersion("cuTensorMapEncodeTiled", (void**)&fn, 12000,
                                     cudaEnableDefault, &qr);
#else
    cudaGetDriverEntryPoint("cuTensorMapEncodeTiled", (void**)&fn, cudaEnableDefault, &qr);
#endif
    return fn;
}

extern "C" void kernel_launch(void* const* d_in, const int* in_sizes, int n_in,
                              void* d_out, int out_size) {
    const float* x  = (const float*)d_in[0];
    const float* W1 = (const float*)d_in[1];
    const float* b1 = (const float*)d_in[2];
    const float* W2 = (const float*)d_in[3];
    const float* b2 = (const float*)d_in[4];
    float* out = (float*)d_out;

    void* w1t_ptr = nullptr; cudaGetSymbolAddress(&w1t_ptr, g_W1t);

    EncodeFn enc = get_encoder();
    CUtensorMap tmB;
    if (enc) {
        // B: g_W1t [c][n][k], box [32k, 256n, 1c]
        cuuint64_t dims[3]    = {EDIM, EDIM, NCLS};
        cuuint64_t strides[2] = {EDIM * 4ull, (cuuint64_t)EDIM * EDIM * 4ull};
        cuuint32_t box[3]     = {32, 256, 1};
        cuuint32_t estr[3]    = {1, 1, 1};
        enc(&tmB, CU_TENSOR_MAP_DATA_TYPE_FLOAT32, 3, w1t_ptr, dims, strides, box, estr,
            CU_TENSOR_MAP_INTERLEAVE_NONE, CU_TENSOR_MAP_SWIZZLE_128B,
            CU_TENSOR_MAP_L2_PROMOTION_L2_128B, CU_TENSOR_MAP_FLOAT_OOB_FILL_NONE);
    }

    cudaFuncSetAttribute(mlp_head_tc, cudaFuncAttributeMaxDynamicSharedMemorySize, SMEM_TOTAL);

    w1_conv<<<dim3(EDIM / 32, EDIM / 32, NCLS), dim3(32, 8)>>>(W1);

    // 512 CTAs (two batches per CTA), 1 CTA/SM (smem- and TMEM-sized)
    mlp_head_tc<<<dim3(BATCH / 2, NCLS), THREADS_TC, SMEM_TOTAL>>>(tmB, x, b1, W2, b2, out);
}

// round 17
// speedup vs baseline: 2.2110x; 2.2110x over previous
#include <cuda_runtime.h>
#include <cuda.h>
#include <cstdint>
#include <math.h>

#define BATCH   16
#define NCLS    64
#define CDF     128
#define EDIM    1024

// ===================== common helpers =====================
__device__ __forceinline__ uint32_t f2tf32(float f) {
    uint32_t u; asm("cvt.rna.tf32.f32 %0, %1;" : "=r"(u) : "f"(f)); return u;
}
__device__ __forceinline__ float gelu_erf(float v) {
    return 0.5f * v * (1.0f + erff(v * 0.7071067811865476f));
}

#if defined(__CUDA_ARCH_FEAT_SM103_ALL) || defined(__CUDA_ARCH_FEAT_SM100_ALL) || defined(__CUDA_ARCH_FEAT_SM101_ALL)
#define TCGEN05_OK 1
#else
#define TCGEN05_OK 0
#endif

// 256MB scratch: W1 transposed + tf32-RNA rounded, layout [c][n][k]
__device__ float g_W1t[(size_t)NCLS * EDIM * EDIM];

// ======================================================================
// Kernel 0: W1 [c][k][n] -> g_W1t [c][n][k], tf32-RNA (32x32 transpose)
// ======================================================================
__global__ void __launch_bounds__(256)
w1_conv(const float* __restrict__ W1) {
    __shared__ float t[32][33];
    const int c  = blockIdx.z;
    const int k0 = blockIdx.x * 32;
    const int n0 = blockIdx.y * 32;
    const float* src = W1 + ((size_t)c << 20);
    float*       dst = g_W1t + ((size_t)c << 20);
    const int tx = threadIdx.x, ty = threadIdx.y;   // 32 x 8
    #pragma unroll
    for (int i = 0; i < 4; ++i)
        t[ty + i * 8][tx] = src[(size_t)(k0 + ty + i * 8) * EDIM + n0 + tx];
    __syncthreads();
    #pragma unroll
    for (int i = 0; i < 4; ++i) {
        float v = t[tx][ty + i * 8];
        dst[(size_t)(n0 + ty + i * 8) * EDIM + k0 + tx] = __uint_as_float(f2tf32(v));
    }
}

// ======================================================================
// cg2 tcgen05 tf32 GEMM (M=256 across CTA pair, B split N/2 per CTA),
// relay-free: follower stagers arrive DIRECTLY on leader's full barrier;
// B TMAs use cta_group::2 completion (auto-targets leader's barrier).
// KT=64 (2 SW128 subs), NSTAGE=3, D ping-pong 2x256 TMEM cols.
// Per-CTA stage ingress: A 32KB + B 32KB = 64KB for 2.1M MACs (-33% vs R6).
// ======================================================================
#define NCHUNK  256        // logical N per chunk (4 chunks)
#define KT      64         // K per stage (2 subs x 4 dispatches)
#define NSTAGE  3
#define THREADS_TC 288     // warps 0-3 epilogue, 4-7 A-stagers, 8 MMA(leader)
#define CLUSTER 2
#define A_TILE_BYTES 32768u   // 128 rows x 64k x 4B (2 subs of 16KB)
#define A_SUB_BYTES  16384u
#define B_TILE_BYTES 32768u   // 128 n x 64k x 4B (2 subs of 16KB)
#define B_SUB_BYTES  16384u
#define B_TX_TOTAL   65536u   // pair total B tx per stage (2 CTAs x 32KB)

#define OFF_TMEM   0
#define OFF_MB     8                     // stage s: full @ 8+16s, empty @ 8+16s+8
#define OFF_CHK    72                    // chunk_done[2] @ 72+8p
#define OFF_EPI    88                    // epi_done[2] (leader-side, count=2)
#define OFF_SB1    256                   // float[1024]
#define OFF_SW2    (256 + 4096)          // float[1024]
#define OFF_TILE   9216                  // 1KB aligned
#define STAGE_BYTES 65536                // A 32KB + B 32KB
#define BTILE_OFF   32768
#define SMEM_TOTAL (OFF_TILE + NSTAGE * STAGE_BYTES)   // 205824 -> 1 CTA/SM

#define TMEM_COLS 512

// idesc (kind::tf32): D=F32(1)@[4], atype=TF32(2)@[7], btype=TF32(2)@[10],
// N>>3 @[17] (N=256), M>>4 @[24] (M=256, cg2)
#define IDESC_TF32_CG2 ((1u<<4) | (2u<<7) | (2u<<10) | ((NCHUNK/8)<<17) | ((256/16)<<24))

#if TCGEN05_OK
__device__ __forceinline__ uint64_t make_desc(uint32_t addr) {
    return (uint64_t(2) << 61) | (uint64_t(1) << 46) | (uint64_t(64) << 32)
         | (uint64_t(1) << 16) | ((uint64_t)(addr >> 4) & 0x3FFF);
}
__device__ __forceinline__ uint32_t smem_u32(const void* p) {
    uint32_t a;
    asm("{ .reg .u64 t; cvta.to.shared.u64 t, %1; cvt.u32.u64 %0, t; }" : "=r"(a) : "l"(p));
    return a;
}
__device__ __forceinline__ void sts128(uint32_t a, uint32_t x, uint32_t y, uint32_t z, uint32_t w) {
    asm volatile("st.shared.v4.b32 [%0], {%1,%2,%3,%4};" :: "r"(a), "r"(x), "r"(y), "r"(z), "r"(w) : "memory");
}
__device__ __forceinline__ void mbar_init(uint32_t a, uint32_t cnt) {
    asm volatile("mbarrier.init.shared.b64 [%0], %1;" :: "r"(a), "r"(cnt) : "memory");
}
__device__ __forceinline__ void mbar_arrive(uint32_t a) {
    asm volatile("mbarrier.arrive.shared.b64 _, [%0];" :: "r"(a) : "memory");
}
// arrive on the same smem offset in cluster CTA 0 (the pair leader)
__device__ __forceinline__ void mbar_arrive_leader(uint32_t a) {
    asm volatile(
        "{\n\t.reg .b32 rem;\n\t"
        "mapa.shared::cluster.u32 rem, %0, 0;\n\t"
        "mbarrier.arrive.shared::cluster.b64 _, [rem];\n\t}"
        :: "r"(a) : "memory");
}
__device__ __forceinline__ void mbar_wait(uint32_t a, uint32_t parity) {
    asm volatile(
        "{\n\t.reg .pred P;\n\t"
        "WL%=:\n\t"
        "mbarrier.try_wait.parity.acquire.cta.shared::cta.b64 P, [%0], %1, 0x989680;\n\t"
        "@P bra.uni WD%=;\n\t"
        "bra.uni WL%=;\n\t"
        "WD%=:\n\t}" :: "r"(a), "r"(parity) : "memory");
}
__device__ __forceinline__ void fence_async_proxy() {
    asm volatile("fence.proxy.async.shared::cta;" ::: "memory");
}
__device__ __forceinline__ void tc_commit_mc_cg2(uint32_t mbar, uint16_t mask) {
    asm volatile("tcgen05.commit.cta_group::2.mbarrier::arrive::one.shared::cluster.multicast::cluster.b64 [%0], %1;"
                 :: "r"(mbar), "h"(mask) : "memory");
}
__device__ __forceinline__ void mma_tf32_ss_cg2(uint32_t d, uint64_t ad, uint64_t bd,
                                                uint32_t idesc, uint32_t enable) {
    asm volatile(
        "{\n\t.reg .pred p;\n\t"
        "setp.ne.u32 p, %5, 0;\n\t"
        "tcgen05.mma.cta_group::2.kind::tf32 [%0], %1, %2, %3, "
        "{%4,%4,%4,%4,%4,%4,%4,%4}, p;\n\t}"
        :: "r"(d), "l"(ad), "l"(bd), "r"(idesc), "r"(0u), "r"(enable) : "memory");
}
// cg2 TMA: data -> issuing CTA's smem; complete_tx -> leader's barrier (bit24 clear)
__device__ __forceinline__ void tma_b_cg2(uint32_t dst, const void* tmap,
                                          int k0, int ng, int c, uint32_t fullb) {
    asm volatile(
        "{\n\t.reg .b32 lb;\n\t"
        "and.b32 lb, %5, 0xFEFFFFFF;\n\t"
        "cp.async.bulk.tensor.3d.cta_group::2.shared::cluster.global.tile"
        ".mbarrier::complete_tx::bytes "
        "[%0], [%1, {%2, %3, %4}], [lb];\n\t}"
        :: "r"(dst), "l"(tmap), "r"(k0), "r"(ng), "r"(c), "r"(fullb) : "memory");
}
#endif  // TCGEN05_OK

__global__ void __launch_bounds__(THREADS_TC, 1)
mlp_head_tc(const __grid_constant__ CUtensorMap tmapB,
            const float* __restrict__ x,
            const float* __restrict__ b1,
            const float* __restrict__ W2,
            const float* __restrict__ b2,
            float* __restrict__ out)
{
#if TCGEN05_OK
    extern __shared__ char smem[];
    const uint32_t sb = smem_u32(smem);

    const int tid  = threadIdx.x;
    const int warp = tid >> 5;
    const int lane = tid & 31;
    const int b    = blockIdx.x;   // cluster pairs (even, odd) batches, same class
    const int c    = blockIdx.y;
    uint32_t rank;                 // 0 = leader (lower N half), 1 = follower (upper)
    asm("mov.u32 %0, %%cluster_ctarank;" : "=r"(rank));

    const float* Abase = x + ((size_t)b * (NCLS * CDF) + (size_t)c * CDF) * EDIM;

    float* sb1s = (float*)(smem + OFF_SB1);
    float* sw2s = (float*)(smem + OFF_SW2);

    if (warp == 8) {
        asm volatile("tcgen05.alloc.cta_group::2.sync.aligned.shared::cta.b32 [%0], %1;"
                     :: "r"(sb + OFF_TMEM), "r"((uint32_t)TMEM_COLS) : "memory");
    }
    if (tid == 0) {
        #pragma unroll
        for (int s = 0; s < NSTAGE; ++s) {
            // full (leader-side meaningful): 2x128 stagers + 1 expect_tx thread
            mbar_init(sb + OFF_MB + s * 16,     257);
            mbar_init(sb + OFF_MB + s * 16 + 8, 1);     // empty: 1 cg2 commit (mc)
        }
        mbar_init(sb + OFF_CHK + 0, 1); mbar_init(sb + OFF_CHK + 8, 1);
        mbar_init(sb + OFF_EPI + 0, 2); mbar_init(sb + OFF_EPI + 8, 2);   // both epilogues
    }
    __syncthreads();
    // both CTAs' barriers live before any cross-CTA arrive / cg2 op
    asm volatile("barrier.cluster.arrive.aligned;" ::: "memory");
    asm volatile("barrier.cluster.wait.aligned;" ::: "memory");

    uint32_t tmem;
    asm volatile("ld.shared.b32 %0, [%1];" : "=r"(tmem) : "r"(sb + OFF_TMEM));

    const int NTILES = 4 * (EDIM / KT);   // 64 stages (4 chunks x 16 k-tiles)

    if (warp >= 4 && warp < 8) {
        // ===== PRODUCERS (warps 4-7): A LDG+cvt+STS (2 subs), B cg2 TMA =====
        const int local = tid - 128;
        const int q  = local & 7;    // 16B quad within 128B sub-row
        const int r8 = local >> 3;   // 0..15

        float4 abuf[16];   // 2 k-subs x 8 row-passes
        auto load_a = [&](int g) {
            const int gi = (g < NTILES) ? g : (NTILES - 1);
            const int k0 = (gi & 15) * KT;
            #pragma unroll
            for (int sub = 0; sub < 2; ++sub) {
                const float* Ak = Abase + k0 + sub * 32 + (size_t)r8 * EDIM + q * 4;
                #pragma unroll
                for (int ps = 0; ps < 8; ++ps)
                    abuf[sub * 8 + ps] = *(const float4*)(Ak + (size_t)ps * 16 * EDIM);
            }
        };

        load_a(0);
        for (int g = 0; g < NTILES; ++g) {
            const int s = g % NSTAGE;
            const int r = g / NSTAGE;
            const uint32_t fullb  = sb + OFF_MB + s * 16;
            const uint32_t emptyb = fullb + 8;
            mbar_wait(emptyb, (r & 1) ^ 1);   // leader MMA done with stage s (mc)

            const uint32_t a_sm = sb + OFF_TILE + s * STAGE_BYTES;
            const uint32_t b_sm = a_sm + BTILE_OFF;

            if (local == 0) {
                // only the LEADER posts expect_tx (all 4 TMAs' tx land on its bar)
                if (rank == 0) {
                    asm volatile("mbarrier.arrive.expect_tx.shared.b64 _, [%0], %1;"
                                 :: "r"(fullb), "r"(B_TX_TOTAL) : "memory");
                }
                const int k0 = (g & 15) * KT;
                const int ng = (g >> 4) * NCHUNK + (int)rank * 128;   // my N half
                #pragma unroll
                for (int sub = 0; sub < 2; ++sub) {
                    tma_b_cg2(b_sm + sub * B_SUB_BYTES, &tmapB,
                              k0 + sub * 32, ng, c, fullb);
                }
            }

            // A tile: 2 subs of (128 rows x 32 k), tf32-RNA, SW128
            #pragma unroll
            for (int sub = 0; sub < 2; ++sub) {
                #pragma unroll
                for (int ps = 0; ps < 8; ++ps) {
                    const int row = ps * 16 + r8;
                    uint32_t off = row * 128 + q * 16;
                    off ^= (off >> 3) & 0x70;
                    const float4 v = abuf[sub * 8 + ps];
                    sts128(a_sm + sub * A_SUB_BYTES + off,
                           f2tf32(v.x), f2tf32(v.y), f2tf32(v.z), f2tf32(v.w));
                }
            }
            fence_async_proxy();
            if (rank == 0) mbar_arrive(fullb);         // leader: local arrive
            else           mbar_arrive_leader(fullb);  // follower: direct remote arrive
            load_a(g + 1);
        }
    } else if (warp == 8) {
        // ================= MMA ISSUE (leader warp 8, lane 0 only) =================
        if (lane == 0 && rank == 0) {
            uint64_t ad[NSTAGE], bd[NSTAGE];
            #pragma unroll
            for (int s = 0; s < NSTAGE; ++s) {
                ad[s] = make_desc(sb + OFF_TILE + s * STAGE_BYTES);
                bd[s] = make_desc(sb + OFF_TILE + s * STAGE_BYTES + BTILE_OFF);
            }
            int g = 0;
            for (int ci = 0; ci < 4; ++ci) {
                const int p = ci & 1;
                if (ci >= 2) {
                    mbar_wait(sb + OFF_EPI + p * 8, 0);   // both epilogues drained D(p)
                    asm volatile("tcgen05.fence::after_thread_sync;" ::: "memory");
                }
                const uint32_t dt = tmem + p * NCHUNK;
                for (int kt = 0; kt < 16; ++kt, ++g) {
                    const int s = g % NSTAGE;
                    const int r = g / NSTAGE;
                    mbar_wait(sb + OFF_MB + s * 16, r & 1);   // pair stage ready
                    #pragma unroll
                    for (int j = 0; j < 8; ++j) {
                        const int sub = j >> 2;
                        const int jj  = j & 3;
                        mma_tf32_ss_cg2(dt,
                                        ad[s] + sub * (A_SUB_BYTES / 16) + jj * 2,
                                        bd[s] + sub * (B_SUB_BYTES / 16) + jj * 2,
                                        IDESC_TF32_CG2, (kt > 0 || j > 0) ? 1u : 0u);
                    }
                    // release stage s in BOTH CTAs when these MMAs complete
                    tc_commit_mc_cg2(sb + OFF_MB + s * 16 + 8, (uint16_t)0x3);
                }
                tc_commit_mc_cg2(sb + OFF_CHK + p * 8, (uint16_t)0x3);  // chunk done
            }
        }
    } else {
        // ================= EPILOGUE (warps 0-3, 128 threads, both CTAs) =========
        #pragma unroll
        for (int i = 0; i < 8; ++i) {
            sb1s[tid + i * 128] = b1[(size_t)c * EDIM + tid + i * 128];
            sw2s[tid + i * 128] = W2[(size_t)c * EDIM + tid + i * 128];
        }
        asm volatile("bar.sync 1, 128;" ::: "memory");

        float accum = 0.0f;
        for (int ci = 0; ci < 4; ++ci) {
            const int p = ci & 1;
            mbar_wait(sb + OFF_CHK + p * 8, (ci >> 1) & 1);
            asm volatile("tcgen05.fence::after_thread_sync;" ::: "memory");

            #pragma unroll
            for (int blk = 0; blk < NCHUNK / 32; ++blk) {
                uint32_t rg[32];
                asm volatile(
                    "tcgen05.ld.sync.aligned.32x32b.x32.b32 "
                    "{%0,%1,%2,%3,%4,%5,%6,%7,%8,%9,%10,%11,%12,%13,%14,%15,"
                    "%16,%17,%18,%19,%20,%21,%22,%23,%24,%25,%26,%27,%28,%29,%30,%31}, [%32];"
                    : "=r"(rg[0]),"=r"(rg[1]),"=r"(rg[2]),"=r"(rg[3]),"=r"(rg[4]),"=r"(rg[5]),
                      "=r"(rg[6]),"=r"(rg[7]),"=r"(rg[8]),"=r"(rg[9]),"=r"(rg[10]),"=r"(rg[11]),
                      "=r"(rg[12]),"=r"(rg[13]),"=r"(rg[14]),"=r"(rg[15]),"=r"(rg[16]),"=r"(rg[17]),
                      "=r"(rg[18]),"=r"(rg[19]),"=r"(rg[20]),"=r"(rg[21]),"=r"(rg[22]),"=r"(rg[23]),
                      "=r"(rg[24]),"=r"(rg[25]),"=r"(rg[26]),"=r"(rg[27]),"=r"(rg[28]),"=r"(rg[29]),
                      "=r"(rg[30]),"=r"(rg[31])
                    : "r"(tmem + p * NCHUNK + blk * 32));
                asm volatile("tcgen05.wait::ld.sync.aligned;" ::: "memory");
                #pragma unroll
                for (int j = 0; j < 32; ++j) {
                    const int col = ci * NCHUNK + blk * 32 + j;
                    float v = __uint_as_float(rg[j]) + sb1s[col];
                    accum += gelu_erf(v) * sw2s[col];
                }
            }
            asm volatile("tcgen05.fence::before_thread_sync;" ::: "memory");
            asm volatile("bar.sync 1, 128;" ::: "memory");   // all 128 done with D(p)
            if (tid == 0) {
                if (rank == 0) mbar_arrive(sb + OFF_EPI + p * 8);
                else           mbar_arrive_leader(sb + OFF_EPI + p * 8);
            }
        }
        const int row = warp * 32 + lane;
        out[(size_t)b * (NCLS * CDF) + (size_t)c * CDF + row] = accum + b2[c];
    }

    __syncthreads();
    if (warp == 8) {
        asm volatile("tcgen05.relinquish_alloc_permit.cta_group::2.sync.aligned;" ::: "memory");
        asm volatile("tcgen05.dealloc.cta_group::2.sync.aligned.b32 %0, %1;"
                     :: "r"(tmem), "r"((uint32_t)TMEM_COLS));
    }
    // pair coupling: no CTA exits while peer MMA/commit may touch its state
    asm volatile("barrier.cluster.arrive.aligned;" ::: "memory");
    asm volatile("barrier.cluster.wait.aligned;" ::: "memory");
#else
    (void)tmapB; (void)x; (void)b1; (void)W2; (void)b2; (void)out;
#endif
}

// ======================================================================
// Host
// ======================================================================
typedef CUresult (*EncodeFn)(CUtensorMap*, CUtensorMapDataType, cuuint32_t, void*,
                             const cuuint64_t*, const cuuint64_t*, const cuuint32_t*,
                             const cuuint32_t*, CUtensorMapInterleave, CUtensorMapSwizzle,
                             CUtensorMapL2promotion, CUtensorMapFloatOOBfill);
static EncodeFn get_encoder() {
    EncodeFn fn = nullptr;
    cudaDriverEntryPointQueryResult qr;
#if CUDART_VERSION >= 12050
    cudaGetDriverEntryPointByVersion("cuTensorMapEncodeTiled", (void**)&fn, 12000,
                                     cudaEnableDefault, &qr);
#else
    cudaGetDriverEntryPoint("cuTensorMapEncodeTiled", (void**)&fn, cudaEnableDefault, &qr);
#endif
    return fn;
}

extern "C" void kernel_launch(void* const* d_in, const int* in_sizes, int n_in,
                              void* d_out, int out_size) {
    const float* x  = (const float*)d_in[0];
    const float* W1 = (const float*)d_in[1];
    const float* b1 = (const float*)d_in[2];
    const float* W2 = (const float*)d_in[3];
    const float* b2 = (const float*)d_in[4];
    float* out = (float*)d_out;

    void* w1t_ptr = nullptr; cudaGetSymbolAddress(&w1t_ptr, g_W1t);

    EncodeFn enc = get_encoder();
    CUtensorMap tmB;
    if (enc) {
        // B: g_W1t [c][n][k], box [32k, 128n, 1c] (one sub of one CTA's N-half)
        cuuint64_t dims[3]    = {EDIM, EDIM, NCLS};
        cuuint64_t strides[2] = {EDIM * 4ull, (cuuint64_t)EDIM * EDIM * 4ull};
        cuuint32_t box[3]     = {32, 128, 1};
        cuuint32_t estr[3]    = {1, 1, 1};
        enc(&tmB, CU_TENSOR_MAP_DATA_TYPE_FLOAT32, 3, w1t_ptr, dims, strides, box, estr,
            CU_TENSOR_MAP_INTERLEAVE_NONE, CU_TENSOR_MAP_SWIZZLE_128B,
            CU_TENSOR_MAP_L2_PROMOTION_L2_128B, CU_TENSOR_MAP_FLOAT_OOB_FILL_NONE);
    }

    cudaFuncSetAttribute(mlp_head_tc, cudaFuncAttributeMaxDynamicSharedMemorySize, SMEM_TOTAL);

    w1_conv<<<dim3(EDIM / 32, EDIM / 32, NCLS), dim3(32, 8)>>>(W1);

    cudaLaunchConfig_t cfg = {};
    cfg.gridDim  = dim3(BATCH, NCLS);          // 1024 CTAs = 512 cg2 pairs
    cfg.blockDim = dim3(THREADS_TC, 1, 1);
    cfg.dynamicSmemBytes = SMEM_TOTAL;
    cfg.stream = 0;
    cudaLaunchAttribute attrs[1];
    attrs[0].id = cudaLaunchAttributeClusterDimension;
    attrs[0].val.clusterDim = {CLUSTER, 1, 1}; // pair = (even b, odd b), same class
    cfg.attrs = attrs;
    cfg.numAttrs = 1;
    cudaLaunchKernelEx(&cfg, mlp_head_tc, tmB, x, b1, W2, b2, out);
}